// round 9
// baseline (speedup 1.0000x reference)
#include <cuda_runtime.h>

#define BB 4
#define CC 32
#define NF 40000
#define NE 80000
#define NV 40000
#define CAP 64          // max bucketed edges per dst node (avg deg 2-6)

// cnt layout: [f2e: NE][e2v: NV][ff: NF][e2f: NF][v2e: NE]  (280000 ints)
#define CNT_TOT (NE + NV + NF + NF + NE)
#define OFF_F2E 0
#define OFF_E2V (NE)
#define OFF_FF  (NE + NV)
#define OFF_E2F (NE + NV + NF)
#define OFF_V2E (NE + NV + NF + NF)

// Persistent scratch (no allocations anywhere)
__device__ float g_xf0[BB * NF * CC];
__device__ float g_xe0[BB * NE * CC];
__device__ float g_xv0[BB * NV * CC];
__device__ float g_xe1[BB * NE * CC];   // F2E output
__device__ float g_xf1[BB * NF * CC];   // FF output
__device__ int   g_cnt[CNT_TOT];
__device__ int   g_bucket[(size_t)CNT_TOT * CAP];

__device__ __forceinline__ unsigned long long ffma2(
    unsigned long long a, unsigned long long b, unsigned long long c) {
    unsigned long long d;
    asm("fma.rn.f32x2 %0, %1, %2, %3;" : "=l"(d) : "l"(a), "l"(b), "l"(c));
    return d;
}
__device__ __forceinline__ unsigned long long pack2(float lo, float hi) {
    unsigned long long u;
    asm("mov.b64 %0, {%1, %2};" : "=l"(u) : "f"(lo), "f"(hi));
    return u;
}
__device__ __forceinline__ void unpack2(unsigned long long u, float& lo, float& hi) {
    asm("mov.b64 {%0, %1}, %2;" : "=f"(lo), "=f"(hi) : "l"(u));
}

__global__ void zero_cnt_kernel(int* __restrict__ cnt, int n4) {
    int i = blockIdx.x * blockDim.x + threadIdx.x;
    if (i < n4) reinterpret_cast<int4*>(cnt)[i] = make_int4(0, 0, 0, 0);
}

// One pass over all 5 edge lists -> disjoint cnt/bucket regions.
struct FillParams {
    const int* edges[5];
    int E[5];          // edge counts
    int start[5];      // exclusive prefix of E
    int off[5];        // dst region offset in cnt/bucket
    int total;
};
__global__ void fill_all_kernel(FillParams fp, int* __restrict__ cnt,
                                int* __restrict__ bucket) {
    int i = blockIdx.x * blockDim.x + threadIdx.x;
    if (i >= fp.total) return;
    int L = 0;
#pragma unroll
    for (int l = 1; l < 5; ++l) L += (i >= fp.start[l]);
    int e = i - fp.start[L];
    const int* eg = fp.edges[L];
    int s = eg[e];
    int d = fp.off[L] + eg[fp.E[L] + e];
    int slot = atomicAdd(&cnt[d], 1);
    if (slot < CAP) bucket[(size_t)d * CAP + slot] = s;
}

// Three input embeddings in one grid. Warp per (node,batch), lane = channel.
struct EmbedParams {
    const float* x[3]; const float* W[3]; const float* b[3]; float* out[3];
    int cin[3];
    int start[3];      // warp-range prefix (in warps)
    int total;         // total warps
};
__global__ void embed_all_kernel(EmbedParams ep) {
    int t = blockIdx.x * blockDim.x + threadIdx.x;
    int w = t >> 5, c = t & 31;
    if (w >= ep.total) return;
    int L = 0;
#pragma unroll
    for (int l = 1; l < 3; ++l) L += (w >= ep.start[l]);
    int node = w - ep.start[L];          // layer-local (batch*node) index
    int cin = ep.cin[L];
    const float* x = ep.x[L] + (size_t)node * cin;
    const float* W = ep.W[L];
    float acc = ep.b[L][c];
    for (int k = 0; k < cin; ++k)
        acc += x[k] * W[k * CC + c];
    ep.out[L][(size_t)node * CC + c] = acc > 0.f ? acc : 0.01f * acc;
}

// Batched fused segment-min gather + residual MLP (up to 3 layers per launch).
// Block = 64 nodes of ONE layer (8 consecutive per warp); block picks its layer
// by grid-range. Packed W in smem (8KB/block); register-tiled FFMA2 MLP.
struct Layer {
    const int* cnt; const int* bucket;
    const float* xs; const float* xd;
    const float* W; const float* bias;
    float* out;
    int Ns, Nd;
    int blockStart;    // first block of this layer
};
struct PhaseParams { Layer L[3]; int nLayers; };

__global__ __launch_bounds__(256, 4) void reduce_mlp_batched(PhaseParams pp) {
    __shared__ unsigned long long sWp[CC][CC];  // [k][lane] = (W[k][lane], W[k+32][lane])
    __shared__ float2 stage[8][BB][CC];         // [warp][batch][k]
    int tid = threadIdx.x;
    int lane = tid & 31, wip = tid >> 5;

    int li = 0;
#pragma unroll
    for (int l = 1; l < 3; ++l)
        li += (l < pp.nLayers && (int)blockIdx.x >= pp.L[l].blockStart);
    const Layer& Ly = pp.L[li];
    const float* __restrict__ W = Ly.W;
    const float* __restrict__ xs = Ly.xs;
    const float* __restrict__ xd = Ly.xd;
    const int* __restrict__ cnt = Ly.cnt;
    const int* __restrict__ bucket = Ly.bucket;
    float* __restrict__ out = Ly.out;
    const int Ns = Ly.Ns, Nd = Ly.Nd;

    for (int k = wip; k < CC; k += 8)
        sWp[k][lane] = pack2(W[k * CC + lane], W[(k + CC) * CC + lane]);
    __syncthreads();

    float bv = Ly.bias[lane];
    const size_t BS = (size_t)Ns * CC;
    const float PINF = __int_as_float(0x7f800000);

    int dBase = (blockIdx.x - Ly.blockStart) * 64 + wip * 8;
#pragma unroll 1
    for (int it = 0; it < 8; ++it) {
        int d = dBase + it;
        if (d >= Nd) break;

        // ---- segment-min gather (chunked x4 for MLP) ----
        int deg = cnt[d];
        if (deg > CAP) deg = CAP;
        const int* bk = bucket + (size_t)d * CAP;

        float mn0 = PINF, mn1 = PINF, mn2 = PINF, mn3 = PINF;
        int i = 0;
        for (; i + 4 <= deg; i += 4) {
            int4 q = *reinterpret_cast<const int4*>(bk + i);  // 16B-aligned
            const float* p0 = xs + (size_t)q.x * CC + lane;
            const float* p1 = xs + (size_t)q.y * CC + lane;
            const float* p2 = xs + (size_t)q.z * CC + lane;
            const float* p3 = xs + (size_t)q.w * CC + lane;
            float a0 = p0[0],      a1 = p1[0],      a2 = p2[0],      a3 = p3[0];
            float b0 = p0[BS],     b1 = p1[BS],     b2 = p2[BS],     b3 = p3[BS];
            float c0 = p0[2 * BS], c1 = p1[2 * BS], c2 = p2[2 * BS], c3 = p3[2 * BS];
            float e0 = p0[3 * BS], e1 = p1[3 * BS], e2 = p2[3 * BS], e3 = p3[3 * BS];
            mn0 = fminf(mn0, fminf(fminf(a0, a1), fminf(a2, a3)));
            mn1 = fminf(mn1, fminf(fminf(b0, b1), fminf(b2, b3)));
            mn2 = fminf(mn2, fminf(fminf(c0, c1), fminf(c2, c3)));
            mn3 = fminf(mn3, fminf(fminf(e0, e1), fminf(e2, e3)));
        }
        for (; i < deg; ++i) {
            int s = bk[i];
            const float* p = xs + (size_t)s * CC + lane;
            mn0 = fminf(mn0, p[0]);
            mn1 = fminf(mn1, p[BS]);
            mn2 = fminf(mn2, p[2 * BS]);
            mn3 = fminf(mn3, p[3 * BS]);
        }
        float mns[BB] = {mn0, mn1, mn2, mn3};

        // ---- stage h = (xv, mv) per batch ----
        float xv[BB];
#pragma unroll
        for (int b = 0; b < BB; ++b) {
            xv[b] = xd[((size_t)b * Nd + d) * CC + lane];
            float m = mns[b];
            float mv = (__float_as_uint(m) == 0x7f800000u) ? 0.f : xv[b] - m;
            stage[wip][b][lane] = make_float2(xv[b], mv);
        }
        __syncwarp();

        // ---- MLP: register-tile 4 W pairs, apply to all 4 batches ----
        unsigned long long acc0[BB], acc1[BB];
#pragma unroll
        for (int b = 0; b < BB; ++b) { acc0[b] = 0ull; acc1[b] = 0ull; }
#pragma unroll
        for (int kt = 0; kt < CC; kt += 4) {
            unsigned long long w0 = sWp[kt][lane],     w1 = sWp[kt + 1][lane];
            unsigned long long w2 = sWp[kt + 2][lane], w3 = sWp[kt + 3][lane];
#pragma unroll
            for (int b = 0; b < BB; ++b) {
                const unsigned long long* hp =
                    reinterpret_cast<const unsigned long long*>(stage[wip][b]);
                acc0[b] = ffma2(hp[kt],     w0, acc0[b]);
                acc1[b] = ffma2(hp[kt + 1], w1, acc1[b]);
                acc0[b] = ffma2(hp[kt + 2], w2, acc0[b]);
                acc1[b] = ffma2(hp[kt + 3], w3, acc1[b]);
            }
        }
#pragma unroll
        for (int b = 0; b < BB; ++b) {
            float l0, h0, l1, h1;
            unpack2(acc0[b], l0, h0);
            unpack2(acc1[b], l1, h1);
            float acc = ((l0 + h0) + (l1 + h1)) + bv;
            float o = xv[b] + (acc > 0.f ? acc : 0.01f * acc);
            out[((size_t)b * Nd + d) * CC + lane] = o;
        }
        __syncwarp();
    }
}

static inline int cdiv(long long a, int b) { return (int)((a + b - 1) / b); }

extern "C" void kernel_launch(void* const* d_in, const int* in_sizes, int n_in,
                              void* d_out, int out_size) {
    const float* x_f = (const float*)d_in[0];
    const float* x_e = (const float*)d_in[1];
    const float* x_v = (const float*)d_in[2];
    // d_in[3] = index_id (identity arange; unused)
    const int* fe = (const int*)d_in[4];
    const int* ev = (const int*)d_in[5];
    const int* ff = (const int*)d_in[6];
    const int* ef = (const int*)d_in[7];
    const int* ve = (const int*)d_in[8];
    const float* Wf = (const float*)d_in[9];   const float* bf = (const float*)d_in[10];
    const float* We = (const float*)d_in[11];  const float* be = (const float*)d_in[12];
    const float* Wv = (const float*)d_in[13];  const float* bv = (const float*)d_in[14];
    const float* W_f2e = (const float*)d_in[15]; const float* b_f2e = (const float*)d_in[16];
    const float* W_e2v = (const float*)d_in[17]; const float* b_e2v = (const float*)d_in[18];
    const float* W_ff  = (const float*)d_in[19]; const float* b_ff  = (const float*)d_in[20];
    const float* W_e2f = (const float*)d_in[21]; const float* b_e2f = (const float*)d_in[22];
    const float* W_v2e = (const float*)d_in[23]; const float* b_v2e = (const float*)d_in[24];

    int E_fe = in_sizes[4] / 2, E_ev = in_sizes[5] / 2, E_ff = in_sizes[6] / 2,
        E_ef = in_sizes[7] / 2, E_ve = in_sizes[8] / 2;

    float* out_xf = (float*)d_out;
    float* out_xe = out_xf + (size_t)BB * NF * CC;
    float* out_xv = out_xe + (size_t)BB * NE * CC;

    float *xf0, *xe0, *xv0, *xe1, *xf1;
    int *cnt, *bucket;
    cudaGetSymbolAddress((void**)&xf0, g_xf0);
    cudaGetSymbolAddress((void**)&xe0, g_xe0);
    cudaGetSymbolAddress((void**)&xv0, g_xv0);
    cudaGetSymbolAddress((void**)&xe1, g_xe1);
    cudaGetSymbolAddress((void**)&xf1, g_xf1);
    cudaGetSymbolAddress((void**)&cnt, g_cnt);
    cudaGetSymbolAddress((void**)&bucket, g_bucket);

    const int TB = 256;

    // ---- 1. zero all counters ----
    zero_cnt_kernel<<<cdiv(CNT_TOT / 4, TB), TB>>>(cnt, CNT_TOT / 4);

    // ---- 2. build all 5 buckets in one pass ----
    FillParams fp;
    fp.edges[0] = fe; fp.edges[1] = ev; fp.edges[2] = ff; fp.edges[3] = ef; fp.edges[4] = ve;
    fp.E[0] = E_fe; fp.E[1] = E_ev; fp.E[2] = E_ff; fp.E[3] = E_ef; fp.E[4] = E_ve;
    fp.start[0] = 0;
    for (int l = 1; l < 5; ++l) fp.start[l] = fp.start[l - 1] + fp.E[l - 1];
    fp.total = fp.start[4] + fp.E[4];
    fp.off[0] = OFF_F2E; fp.off[1] = OFF_E2V; fp.off[2] = OFF_FF;
    fp.off[3] = OFF_E2F; fp.off[4] = OFF_V2E;
    fill_all_kernel<<<cdiv(fp.total, TB), TB>>>(fp, cnt, bucket);

    // ---- 3. all embeddings in one launch ----
    EmbedParams ep;
    ep.x[0] = x_f; ep.x[1] = x_e; ep.x[2] = x_v;
    ep.W[0] = Wf;  ep.W[1] = We;  ep.W[2] = Wv;
    ep.b[0] = bf;  ep.b[1] = be;  ep.b[2] = bv;
    ep.out[0] = xf0; ep.out[1] = xe0; ep.out[2] = xv0;
    ep.cin[0] = 4; ep.cin[1] = 6; ep.cin[2] = 3;
    ep.start[0] = 0; ep.start[1] = BB * NF; ep.start[2] = BB * NF + BB * NE;
    ep.total = BB * (NF + NE + NV);
    embed_all_kernel<<<cdiv((long long)ep.total * 32, TB), TB>>>(ep);

    // ---- 4. Phase B: F2E + E2V + FF in one launch ----
    PhaseParams pb;
    pb.nLayers = 3;
    pb.L[0] = { cnt + OFF_F2E, bucket + (size_t)OFF_F2E * CAP, xf0, xe0,
                W_f2e, b_f2e, xe1, NF, NE, 0 };
    pb.L[1] = { cnt + OFF_E2V, bucket + (size_t)OFF_E2V * CAP, xe0, xv0,
                W_e2v, b_e2v, out_xv, NE, NV, cdiv(NE, 64) };
    pb.L[2] = { cnt + OFF_FF, bucket + (size_t)OFF_FF * CAP, xf0, xf0,
                W_ff, b_ff, xf1, NF, NF, cdiv(NE, 64) + cdiv(NV, 64) };
    int nbB = cdiv(NE, 64) + cdiv(NV, 64) + cdiv(NF, 64);
    reduce_mlp_batched<<<nbB, 256>>>(pb);

    // ---- 5. Phase C: E2F + V2E in one launch ----
    PhaseParams pc;
    pc.nLayers = 2;
    pc.L[0] = { cnt + OFF_E2F, bucket + (size_t)OFF_E2F * CAP, xe1, xf1,
                W_e2f, b_e2f, out_xf, NE, NF, 0 };
    pc.L[1] = { cnt + OFF_V2E, bucket + (size_t)OFF_V2E * CAP, out_xv, xe1,
                W_v2e, b_v2e, out_xe, NV, NE, cdiv(NF, 64) };
    pc.L[2] = pc.L[1];   // unused slot (guarded by nLayers)
    int nbC = cdiv(NF, 64) + cdiv(NE, 64);
    reduce_mlp_batched<<<nbC, 256>>>(pc);
}

// round 10
// speedup vs baseline: 1.4530x; 1.4530x over previous
#include <cuda_runtime.h>

#define BB 4
#define CC 32
#define NF 40000
#define NE 80000
#define NV 40000
#define CAP 64          // max bucketed edges per dst node (avg deg 2-6)
#define NDMAX NE        // largest dst-node count

// Persistent scratch (no allocations anywhere)
__device__ float g_xf0[BB * NF * CC];
__device__ float g_xe0[BB * NE * CC];
__device__ float g_xv0[BB * NV * CC];
__device__ float g_xe1[BB * NE * CC];   // F2E output
__device__ float g_xf1[BB * NF * CC];   // FF output
__device__ int   g_cnt[NDMAX];          // per-dst edge counter
__device__ int   g_bucket[(size_t)NDMAX * CAP];  // per-dst src lists

__device__ __forceinline__ unsigned long long ffma2(
    unsigned long long a, unsigned long long b, unsigned long long c) {
    unsigned long long d;
    asm("fma.rn.f32x2 %0, %1, %2, %3;" : "=l"(d) : "l"(a), "l"(b), "l"(c));
    return d;
}
__device__ __forceinline__ unsigned long long pack2(float lo, float hi) {
    unsigned long long u;
    asm("mov.b64 %0, {%1, %2};" : "=l"(u) : "f"(lo), "f"(hi));
    return u;
}
__device__ __forceinline__ void unpack2(unsigned long long u, float& lo, float& hi) {
    asm("mov.b64 {%0, %1}, %2;" : "=f"(lo), "=f"(hi) : "l"(u));
}

// out[b,n,c] = leaky_relu(x[b,n,:] @ W + bias), warp per node, lane = channel.
template <int CIN>
__global__ void embed_kernel(const float* __restrict__ x, const float* __restrict__ W,
                             const float* __restrict__ bias, float* __restrict__ out,
                             int nNodes) {
    int t = blockIdx.x * blockDim.x + threadIdx.x;
    int node = t >> 5, c = t & 31;
    if (node >= nNodes) return;
    float acc = bias[c];
#pragma unroll
    for (int k = 0; k < CIN; ++k)
        acc += x[node * CIN + k] * W[k * CC + c];
    out[t] = acc > 0.f ? acc : 0.01f * acc;
}

__global__ void zero_cnt_kernel(int* __restrict__ cnt, int n4) {
    int i = blockIdx.x * blockDim.x + threadIdx.x;
    if (i < n4) reinterpret_cast<int4*>(cnt)[i] = make_int4(0, 0, 0, 0);
}

// Thread per edge: append src to dst's bucket.
__global__ void fill_kernel(const int* __restrict__ edges, int E,
                            int* __restrict__ cnt, int* __restrict__ bucket) {
    int i = blockIdx.x * blockDim.x + threadIdx.x;
    if (i >= E) return;
    int s = edges[i];
    int d = edges[E + i];
    int slot = atomicAdd(&cnt[d], 1);
    if (slot < CAP) bucket[(size_t)d * CAP + slot] = s;
}

// Fused segment-min gather + residual MLP.
// Block = 64 nodes (8 consecutive per warp). Packed W in smem (8KB/block).
// MLP h operands read as LDS.128 broadcasts (two FFMA2 operands per LDS) —
// halves the dominant shared-pipe traffic (ncu: L1 ~80% on this kernel).
//   maxes[b,c] = (empty) ? 0 : x_dst[b,c] - min_src[b,c]
//   out[b,:]   = x_dst + leaky_relu(concat(x_dst, maxes) @ W[64,32] + bias)
__global__ __launch_bounds__(256, 4) void reduce_mlp_kernel(
    const int* __restrict__ cnt, const int* __restrict__ bucket,
    const float* __restrict__ xs, const float* __restrict__ xd,
    const float* __restrict__ W, const float* __restrict__ bias,
    float* __restrict__ out, int Ns, int Nd) {
    __shared__ unsigned long long sWp[CC][CC];       // [k][lane] = (W[k][lane], W[k+32][lane])
    __shared__ __align__(16) float2 stage[8][BB][CC];// [warp][batch][k]
    int tid = threadIdx.x;
    int lane = tid & 31, wip = tid >> 5;

    for (int k = wip; k < CC; k += 8)
        sWp[k][lane] = pack2(W[k * CC + lane], W[(k + CC) * CC + lane]);
    __syncthreads();

    float bv = bias[lane];
    const size_t BS = (size_t)Ns * CC;   // batch stride in xs
    const float PINF = __int_as_float(0x7f800000);

    int dBase = blockIdx.x * 64 + wip * 8;
#pragma unroll 1
    for (int it = 0; it < 8; ++it) {
        int d = dBase + it;
        if (d >= Nd) break;

        // ---- segment-min gather (chunked x4 for MLP) ----
        int deg = cnt[d];
        if (deg > CAP) deg = CAP;
        const int* bk = bucket + (size_t)d * CAP;

        float mn0 = PINF, mn1 = PINF, mn2 = PINF, mn3 = PINF;
        int i = 0;
        for (; i + 4 <= deg; i += 4) {
            int4 q = *reinterpret_cast<const int4*>(bk + i);  // 16B-aligned
            const float* p0 = xs + (size_t)q.x * CC + lane;
            const float* p1 = xs + (size_t)q.y * CC + lane;
            const float* p2 = xs + (size_t)q.z * CC + lane;
            const float* p3 = xs + (size_t)q.w * CC + lane;
            float a0 = p0[0],      a1 = p1[0],      a2 = p2[0],      a3 = p3[0];
            float b0 = p0[BS],     b1 = p1[BS],     b2 = p2[BS],     b3 = p3[BS];
            float c0 = p0[2 * BS], c1 = p1[2 * BS], c2 = p2[2 * BS], c3 = p3[2 * BS];
            float e0 = p0[3 * BS], e1 = p1[3 * BS], e2 = p2[3 * BS], e3 = p3[3 * BS];
            mn0 = fminf(mn0, fminf(fminf(a0, a1), fminf(a2, a3)));
            mn1 = fminf(mn1, fminf(fminf(b0, b1), fminf(b2, b3)));
            mn2 = fminf(mn2, fminf(fminf(c0, c1), fminf(c2, c3)));
            mn3 = fminf(mn3, fminf(fminf(e0, e1), fminf(e2, e3)));
        }
        for (; i < deg; ++i) {
            int s = bk[i];
            const float* p = xs + (size_t)s * CC + lane;
            mn0 = fminf(mn0, p[0]);
            mn1 = fminf(mn1, p[BS]);
            mn2 = fminf(mn2, p[2 * BS]);
            mn3 = fminf(mn3, p[3 * BS]);
        }
        float mns[BB] = {mn0, mn1, mn2, mn3};

        // ---- stage h = (xv, mv) per batch ----
        float xv[BB];
#pragma unroll
        for (int b = 0; b < BB; ++b) {
            xv[b] = xd[((size_t)b * Nd + d) * CC + lane];
            float m = mns[b];
            float mv = (__float_as_uint(m) == 0x7f800000u) ? 0.f : xv[b] - m;
            stage[wip][b][lane] = make_float2(xv[b], mv);
        }
        __syncwarp();

        // ---- MLP: register-tile 4 W pairs; h via LDS.128 broadcast (2 pairs/load) ----
        unsigned long long acc0[BB], acc1[BB];
#pragma unroll
        for (int b = 0; b < BB; ++b) { acc0[b] = 0ull; acc1[b] = 0ull; }
#pragma unroll
        for (int kt = 0; kt < CC; kt += 4) {
            unsigned long long w0 = sWp[kt][lane],     w1 = sWp[kt + 1][lane];
            unsigned long long w2 = sWp[kt + 2][lane], w3 = sWp[kt + 3][lane];
#pragma unroll
            for (int b = 0; b < BB; ++b) {
                const ulonglong2* hp2 =
                    reinterpret_cast<const ulonglong2*>(stage[wip][b]);
                ulonglong2 h01 = hp2[kt / 2];       // (h[kt], h[kt+1])
                ulonglong2 h23 = hp2[kt / 2 + 1];   // (h[kt+2], h[kt+3])
                acc0[b] = ffma2(h01.x, w0, acc0[b]);
                acc1[b] = ffma2(h01.y, w1, acc1[b]);
                acc0[b] = ffma2(h23.x, w2, acc0[b]);
                acc1[b] = ffma2(h23.y, w3, acc1[b]);
            }
        }
#pragma unroll
        for (int b = 0; b < BB; ++b) {
            float l0, h0, l1, h1;
            unpack2(acc0[b], l0, h0);
            unpack2(acc1[b], l1, h1);
            float acc = ((l0 + h0) + (l1 + h1)) + bv;
            float o = xv[b] + (acc > 0.f ? acc : 0.01f * acc);
            out[((size_t)b * Nd + d) * CC + lane] = o;
        }
        __syncwarp();
    }
}

static inline int cdiv(long long a, int b) { return (int)((a + b - 1) / b); }

extern "C" void kernel_launch(void* const* d_in, const int* in_sizes, int n_in,
                              void* d_out, int out_size) {
    const float* x_f = (const float*)d_in[0];
    const float* x_e = (const float*)d_in[1];
    const float* x_v = (const float*)d_in[2];
    // d_in[3] = index_id (identity arange; unused)
    const int* fe = (const int*)d_in[4];
    const int* ev = (const int*)d_in[5];
    const int* ff = (const int*)d_in[6];
    const int* ef = (const int*)d_in[7];
    const int* ve = (const int*)d_in[8];
    const float* Wf = (const float*)d_in[9];   const float* bf = (const float*)d_in[10];
    const float* We = (const float*)d_in[11];  const float* be = (const float*)d_in[12];
    const float* Wv = (const float*)d_in[13];  const float* bv = (const float*)d_in[14];
    const float* W_f2e = (const float*)d_in[15]; const float* b_f2e = (const float*)d_in[16];
    const float* W_e2v = (const float*)d_in[17]; const float* b_e2v = (const float*)d_in[18];
    const float* W_ff  = (const float*)d_in[19]; const float* b_ff  = (const float*)d_in[20];
    const float* W_e2f = (const float*)d_in[21]; const float* b_e2f = (const float*)d_in[22];
    const float* W_v2e = (const float*)d_in[23]; const float* b_v2e = (const float*)d_in[24];

    int E_fe = in_sizes[4] / 2, E_ev = in_sizes[5] / 2, E_ff = in_sizes[6] / 2,
        E_ef = in_sizes[7] / 2, E_ve = in_sizes[8] / 2;

    float* out_xf = (float*)d_out;
    float* out_xe = out_xf + (size_t)BB * NF * CC;
    float* out_xv = out_xe + (size_t)BB * NE * CC;

    float *xf0, *xe0, *xv0, *xe1, *xf1;
    int *cnt, *bucket;
    cudaGetSymbolAddress((void**)&xf0, g_xf0);
    cudaGetSymbolAddress((void**)&xe0, g_xe0);
    cudaGetSymbolAddress((void**)&xv0, g_xv0);
    cudaGetSymbolAddress((void**)&xe1, g_xe1);
    cudaGetSymbolAddress((void**)&xf1, g_xf1);
    cudaGetSymbolAddress((void**)&cnt, g_cnt);
    cudaGetSymbolAddress((void**)&bucket, g_bucket);

    const int TB = 256;

    // ---- input embeddings ----
    embed_kernel<4><<<cdiv((long long)BB * NF * 32, TB), TB>>>(x_f, Wf, bf, xf0, BB * NF);
    embed_kernel<6><<<cdiv((long long)BB * NE * 32, TB), TB>>>(x_e, We, be, xe0, BB * NE);
    embed_kernel<3><<<cdiv((long long)BB * NV * 32, TB), TB>>>(x_v, Wv, bv, xv0, BB * NV);

    // ---- F2E: src=xf0 (Nf), dst=xe0 (Ne) -> xe1 ----
    zero_cnt_kernel<<<cdiv(NE / 4, TB), TB>>>(cnt, NE / 4);
    fill_kernel<<<cdiv(E_fe, TB), TB>>>(fe, E_fe, cnt, bucket);
    reduce_mlp_kernel<<<cdiv(NE, 64), 256>>>(cnt, bucket, xf0, xe0, W_f2e, b_f2e, xe1, NF, NE);

    // ---- E2V: src=xe0 (Ne), dst=xv0 (Nv) -> out_xv ----
    zero_cnt_kernel<<<cdiv(NV / 4, TB), TB>>>(cnt, NV / 4);
    fill_kernel<<<cdiv(E_ev, TB), TB>>>(ev, E_ev, cnt, bucket);
    reduce_mlp_kernel<<<cdiv(NV, 64), 256>>>(cnt, bucket, xe0, xv0, W_e2v, b_e2v, out_xv, NE, NV);

    // ---- FF: src=dst=xf0 -> xf1 ----
    zero_cnt_kernel<<<cdiv(NF / 4, TB), TB>>>(cnt, NF / 4);
    fill_kernel<<<cdiv(E_ff, TB), TB>>>(ff, E_ff, cnt, bucket);
    reduce_mlp_kernel<<<cdiv(NF, 64), 256>>>(cnt, bucket, xf0, xf0, W_ff, b_ff, xf1, NF, NF);

    // ---- E2F: src=xe1, dst=xf1 -> out_xf ----
    zero_cnt_kernel<<<cdiv(NF / 4, TB), TB>>>(cnt, NF / 4);
    fill_kernel<<<cdiv(E_ef, TB), TB>>>(ef, E_ef, cnt, bucket);
    reduce_mlp_kernel<<<cdiv(NF, 64), 256>>>(cnt, bucket, xe1, xf1, W_e2f, b_e2f, out_xf, NE, NF);

    // ---- V2E: src=out_xv, dst=xe1 -> out_xe ----
    zero_cnt_kernel<<<cdiv(NE / 4, TB), TB>>>(cnt, NE / 4);
    fill_kernel<<<cdiv(E_ve, TB), TB>>>(ve, E_ve, cnt, bucket);
    reduce_mlp_kernel<<<cdiv(NE, 64), 256>>>(cnt, bucket, out_xv, xe1, W_v2e, b_v2e, out_xe, NV, NE);
}

// round 11
// speedup vs baseline: 1.5031x; 1.0345x over previous
#include <cuda_runtime.h>

#define BB 4
#define CC 32
#define NF 40000
#define NE 80000
#define NV 40000
#define CAP 32          // max bucketed edges per dst node (avg deg 2-6; P(>32)~1e-15)

// cnt layout: [f2e: NE][e2v: NV][ff: NF][e2f: NF][v2e: NE]
#define CNT_TOT (NE + NV + NF + NF + NE)
#define OFF_F2E 0
#define OFF_E2V (NE)
#define OFF_FF  (NE + NV)
#define OFF_E2F (NE + NV + NF)
#define OFF_V2E (NE + NV + NF + NF)

// Persistent scratch (no allocations anywhere)
__device__ float g_xf0[BB * NF * CC];
__device__ float g_xe0[BB * NE * CC];
__device__ float g_xv0[BB * NV * CC];
__device__ float g_xe1[BB * NE * CC];   // F2E output
__device__ float g_xf1[BB * NF * CC];   // FF output
__device__ int   g_cnt[CNT_TOT];
__device__ int   g_bucket[(size_t)CNT_TOT * CAP];

__device__ __forceinline__ unsigned long long ffma2(
    unsigned long long a, unsigned long long b, unsigned long long c) {
    unsigned long long d;
    asm("fma.rn.f32x2 %0, %1, %2, %3;" : "=l"(d) : "l"(a), "l"(b), "l"(c));
    return d;
}
__device__ __forceinline__ unsigned long long pack2(float lo, float hi) {
    unsigned long long u;
    asm("mov.b64 %0, {%1, %2};" : "=l"(u) : "f"(lo), "f"(hi));
    return u;
}
__device__ __forceinline__ void unpack2(unsigned long long u, float& lo, float& hi) {
    asm("mov.b64 {%0, %1}, %2;" : "=f"(lo), "=f"(hi) : "l"(u));
}

// out[b,n,c] = leaky_relu(x[b,n,:] @ W + bias), warp per node, lane = channel.
template <int CIN>
__global__ void embed_kernel(const float* __restrict__ x, const float* __restrict__ W,
                             const float* __restrict__ bias, float* __restrict__ out,
                             int nNodes) {
    int t = blockIdx.x * blockDim.x + threadIdx.x;
    int node = t >> 5, c = t & 31;
    if (node >= nNodes) return;
    float acc = bias[c];
#pragma unroll
    for (int k = 0; k < CIN; ++k)
        acc += x[node * CIN + k] * W[k * CC + c];
    out[t] = acc > 0.f ? acc : 0.01f * acc;
}

__global__ void zero_cnt_kernel(int* __restrict__ cnt, int n4) {
    int i = blockIdx.x * blockDim.x + threadIdx.x;
    if (i < n4) reinterpret_cast<int4*>(cnt)[i] = make_int4(0, 0, 0, 0);
}

// Thread per edge: append src to dst's bucket (region pointers passed in).
__global__ void fill_kernel(const int* __restrict__ edges, int E,
                            int* __restrict__ cnt, int* __restrict__ bucket) {
    int i = blockIdx.x * blockDim.x + threadIdx.x;
    if (i >= E) return;
    int s = edges[i];
    int d = edges[E + i];
    int slot = atomicAdd(&cnt[d], 1);
    if (slot < CAP) bucket[(size_t)d * CAP + slot] = s;
}

// Fused segment-min gather + residual MLP. Block = 64 nodes (8 per warp).
// Per-node dependent chain cnt->bucket->features is broken by prefetching the
// next node's cnt + first bucket chunk during the current node's gather/MLP.
//   maxes[b,c] = (empty) ? 0 : x_dst[b,c] - min_src[b,c]
//   out[b,:]   = x_dst + leaky_relu(concat(x_dst, maxes) @ W[64,32] + bias)
__global__ __launch_bounds__(256, 4) void reduce_mlp_kernel(
    const int* __restrict__ cnt, const int* __restrict__ bucket,
    const float* __restrict__ xs, const float* __restrict__ xd,
    const float* __restrict__ W, const float* __restrict__ bias,
    float* __restrict__ out, int Ns, int Nd) {
    __shared__ unsigned long long sWp[CC][CC];       // [k][lane] = (W[k][lane], W[k+32][lane])
    __shared__ __align__(16) float2 stage[8][BB][CC];// [warp][batch][k]
    int tid = threadIdx.x;
    int lane = tid & 31, wip = tid >> 5;

    for (int k = wip; k < CC; k += 8)
        sWp[k][lane] = pack2(W[k * CC + lane], W[(k + CC) * CC + lane]);
    __syncthreads();

    float bv = bias[lane];
    const size_t BS = (size_t)Ns * CC;   // batch stride in xs
    const float PINF = __int_as_float(0x7f800000);

    int dBase = blockIdx.x * 64 + wip * 8;

    // Prefetch chain-head for the first node.
    int degN = 0;
    int4 qN = make_int4(0, 0, 0, 0);
    if (dBase < Nd) {
        degN = cnt[dBase];
        qN = *reinterpret_cast<const int4*>(bucket + (size_t)dBase * CAP);
    }

#pragma unroll 1
    for (int it = 0; it < 8; ++it) {
        int d = dBase + it;
        if (d >= Nd) break;

        int deg = degN;
        if (deg > CAP) deg = CAP;
        int4 qA = qN;

        // Prefetch next node's cnt + first bucket chunk (overlaps this node's work).
        if (it < 7 && d + 1 < Nd) {
            degN = cnt[d + 1];
            qN = *reinterpret_cast<const int4*>(bucket + (size_t)(d + 1) * CAP);
        }

        // x_dst loads (independent of bucket chain) issued early.
        float xv[BB];
#pragma unroll
        for (int b = 0; b < BB; ++b)
            xv[b] = xd[((size_t)b * Nd + d) * CC + lane];

        // ---- segment-min gather (chunks of 4; first chunk prefetched) ----
        const int* bk = bucket + (size_t)d * CAP;
        float mn0 = PINF, mn1 = PINF, mn2 = PINF, mn3 = PINF;
        int i = 0;
        if (deg >= 4) {
            int4 q = qA;
            for (;;) {
                const float* p0 = xs + (size_t)q.x * CC + lane;
                const float* p1 = xs + (size_t)q.y * CC + lane;
                const float* p2 = xs + (size_t)q.z * CC + lane;
                const float* p3 = xs + (size_t)q.w * CC + lane;
                float a0 = p0[0],      a1 = p1[0],      a2 = p2[0],      a3 = p3[0];
                float b0 = p0[BS],     b1 = p1[BS],     b2 = p2[BS],     b3 = p3[BS];
                float c0 = p0[2 * BS], c1 = p1[2 * BS], c2 = p2[2 * BS], c3 = p3[2 * BS];
                float e0 = p0[3 * BS], e1 = p1[3 * BS], e2 = p2[3 * BS], e3 = p3[3 * BS];
                mn0 = fminf(mn0, fminf(fminf(a0, a1), fminf(a2, a3)));
                mn1 = fminf(mn1, fminf(fminf(b0, b1), fminf(b2, b3)));
                mn2 = fminf(mn2, fminf(fminf(c0, c1), fminf(c2, c3)));
                mn3 = fminf(mn3, fminf(fminf(e0, e1), fminf(e2, e3)));
                i += 4;
                if (i + 4 > deg) break;
                q = *reinterpret_cast<const int4*>(bk + i);
            }
        }
        for (; i < deg; ++i) {
            int s = bk[i];
            const float* p = xs + (size_t)s * CC + lane;
            mn0 = fminf(mn0, p[0]);
            mn1 = fminf(mn1, p[BS]);
            mn2 = fminf(mn2, p[2 * BS]);
            mn3 = fminf(mn3, p[3 * BS]);
        }
        float mns[BB] = {mn0, mn1, mn2, mn3};

        // ---- stage h = (xv, mv) per batch ----
#pragma unroll
        for (int b = 0; b < BB; ++b) {
            float m = mns[b];
            float mv = (__float_as_uint(m) == 0x7f800000u) ? 0.f : xv[b] - m;
            stage[wip][b][lane] = make_float2(xv[b], mv);
        }
        __syncwarp();

        // ---- MLP: register-tile 4 W pairs; h via LDS.128 broadcast ----
        unsigned long long acc0[BB], acc1[BB];
#pragma unroll
        for (int b = 0; b < BB; ++b) { acc0[b] = 0ull; acc1[b] = 0ull; }
#pragma unroll
        for (int kt = 0; kt < CC; kt += 4) {
            unsigned long long w0 = sWp[kt][lane],     w1 = sWp[kt + 1][lane];
            unsigned long long w2 = sWp[kt + 2][lane], w3 = sWp[kt + 3][lane];
#pragma unroll
            for (int b = 0; b < BB; ++b) {
                const ulonglong2* hp2 =
                    reinterpret_cast<const ulonglong2*>(stage[wip][b]);
                ulonglong2 h01 = hp2[kt / 2];
                ulonglong2 h23 = hp2[kt / 2 + 1];
                acc0[b] = ffma2(h01.x, w0, acc0[b]);
                acc1[b] = ffma2(h01.y, w1, acc1[b]);
                acc0[b] = ffma2(h23.x, w2, acc0[b]);
                acc1[b] = ffma2(h23.y, w3, acc1[b]);
            }
        }
#pragma unroll
        for (int b = 0; b < BB; ++b) {
            float l0, h0, l1, h1;
            unpack2(acc0[b], l0, h0);
            unpack2(acc1[b], l1, h1);
            float acc = ((l0 + h0) + (l1 + h1)) + bv;
            float o = xv[b] + (acc > 0.f ? acc : 0.01f * acc);
            out[((size_t)b * Nd + d) * CC + lane] = o;
        }
        __syncwarp();
    }
}

static inline int cdiv(long long a, int b) { return (int)((a + b - 1) / b); }

extern "C" void kernel_launch(void* const* d_in, const int* in_sizes, int n_in,
                              void* d_out, int out_size) {
    const float* x_f = (const float*)d_in[0];
    const float* x_e = (const float*)d_in[1];
    const float* x_v = (const float*)d_in[2];
    // d_in[3] = index_id (identity arange; unused)
    const int* fe = (const int*)d_in[4];
    const int* ev = (const int*)d_in[5];
    const int* ff = (const int*)d_in[6];
    const int* ef = (const int*)d_in[7];
    const int* ve = (const int*)d_in[8];
    const float* Wf = (const float*)d_in[9];   const float* bf = (const float*)d_in[10];
    const float* We = (const float*)d_in[11];  const float* be = (const float*)d_in[12];
    const float* Wv = (const float*)d_in[13];  const float* bv = (const float*)d_in[14];
    const float* W_f2e = (const float*)d_in[15]; const float* b_f2e = (const float*)d_in[16];
    const float* W_e2v = (const float*)d_in[17]; const float* b_e2v = (const float*)d_in[18];
    const float* W_ff  = (const float*)d_in[19]; const float* b_ff  = (const float*)d_in[20];
    const float* W_e2f = (const float*)d_in[21]; const float* b_e2f = (const float*)d_in[22];
    const float* W_v2e = (const float*)d_in[23]; const float* b_v2e = (const float*)d_in[24];

    int E_fe = in_sizes[4] / 2, E_ev = in_sizes[5] / 2, E_ff = in_sizes[6] / 2,
        E_ef = in_sizes[7] / 2, E_ve = in_sizes[8] / 2;

    float* out_xf = (float*)d_out;
    float* out_xe = out_xf + (size_t)BB * NF * CC;
    float* out_xv = out_xe + (size_t)BB * NE * CC;

    float *xf0, *xe0, *xv0, *xe1, *xf1;
    int *cnt, *bucket;
    cudaGetSymbolAddress((void**)&xf0, g_xf0);
    cudaGetSymbolAddress((void**)&xe0, g_xe0);
    cudaGetSymbolAddress((void**)&xv0, g_xv0);
    cudaGetSymbolAddress((void**)&xe1, g_xe1);
    cudaGetSymbolAddress((void**)&xf1, g_xf1);
    cudaGetSymbolAddress((void**)&cnt, g_cnt);
    cudaGetSymbolAddress((void**)&bucket, g_bucket);

    const int TB = 256;

    // ---- zero ALL counters once, then build all 5 buckets up front ----
    zero_cnt_kernel<<<cdiv(CNT_TOT / 4, TB), TB>>>(cnt, CNT_TOT / 4);
    fill_kernel<<<cdiv(E_fe, TB), TB>>>(fe, E_fe, cnt + OFF_F2E, bucket + (size_t)OFF_F2E * CAP);
    fill_kernel<<<cdiv(E_ev, TB), TB>>>(ev, E_ev, cnt + OFF_E2V, bucket + (size_t)OFF_E2V * CAP);
    fill_kernel<<<cdiv(E_ff, TB), TB>>>(ff, E_ff, cnt + OFF_FF,  bucket + (size_t)OFF_FF  * CAP);
    fill_kernel<<<cdiv(E_ef, TB), TB>>>(ef, E_ef, cnt + OFF_E2F, bucket + (size_t)OFF_E2F * CAP);
    fill_kernel<<<cdiv(E_ve, TB), TB>>>(ve, E_ve, cnt + OFF_V2E, bucket + (size_t)OFF_V2E * CAP);

    // ---- input embeddings ----
    embed_kernel<4><<<cdiv((long long)BB * NF * 32, TB), TB>>>(x_f, Wf, bf, xf0, BB * NF);
    embed_kernel<6><<<cdiv((long long)BB * NE * 32, TB), TB>>>(x_e, We, be, xe0, BB * NE);
    embed_kernel<3><<<cdiv((long long)BB * NV * 32, TB), TB>>>(x_v, Wv, bv, xv0, BB * NV);

    // ---- layers ----
    reduce_mlp_kernel<<<cdiv(NE, 64), 256>>>(cnt + OFF_F2E, bucket + (size_t)OFF_F2E * CAP,
                                             xf0, xe0, W_f2e, b_f2e, xe1, NF, NE);
    reduce_mlp_kernel<<<cdiv(NV, 64), 256>>>(cnt + OFF_E2V, bucket + (size_t)OFF_E2V * CAP,
                                             xe0, xv0, W_e2v, b_e2v, out_xv, NE, NV);
    reduce_mlp_kernel<<<cdiv(NF, 64), 256>>>(cnt + OFF_FF, bucket + (size_t)OFF_FF * CAP,
                                             xf0, xf0, W_ff, b_ff, xf1, NF, NF);
    reduce_mlp_kernel<<<cdiv(NF, 64), 256>>>(cnt + OFF_E2F, bucket + (size_t)OFF_E2F * CAP,
                                             xe1, xf1, W_e2f, b_e2f, out_xf, NE, NF);
    reduce_mlp_kernel<<<cdiv(NE, 64), 256>>>(cnt + OFF_V2E, bucket + (size_t)OFF_V2E * CAP,
                                             out_xv, xe1, W_v2e, b_v2e, out_xe, NV, NE);
}